// round 1
// baseline (speedup 1.0000x reference)
#include <cuda_runtime.h>
#include <cuda_bf16.h>

// Problem constants
#define BB    16
#define CC    96
#define HH    112
#define WW    112
#define NPIX  (HH*WW)        // 12544
#define WS    7
#define WN    16             // windows per dim
#define HEADS 3
#define DH    32
#define NWIN  (WN*WN)        // 256 windows per image
#define SCALE 0.17677669529663689f   // 32^-0.5

// Scratch (static device globals; allocation-free at launch time)
__device__ float g_q [BB*CC*NPIX];
__device__ float g_k [BB*CC*NPIX];
__device__ float g_v [BB*CC*NPIX];
__device__ float g_ao[BB*CC*NPIX];
__device__ float g_act[BB*CC*NWIN];
__device__ float g_par[BB*HEADS*NWIN*4];   // sclx, scly, ox(px units), oy(px units)

// ---------------------------------------------------------------------------
// Kernel 1: 7x7 window mean pooling + leaky_relu -> g_act[b][c][wy][wx]
// ---------------------------------------------------------------------------
__global__ __launch_bounds__(128) void k_pool(const float* __restrict__ x) {
    int wy = blockIdx.x, c = blockIdx.y, b = blockIdx.z;
    int tid = threadIdx.x;
    __shared__ float s[112];
    if (tid < 112) {
        const float* p = x + ((b*CC + c)*HH + wy*WS)*WW + tid;
        float v = 0.f;
        #pragma unroll
        for (int r = 0; r < WS; r++) v += p[r*WW];
        s[tid] = v;
    }
    __syncthreads();
    if (tid < WN) {
        float v = 0.f;
        #pragma unroll
        for (int i = 0; i < WS; i++) v += s[tid*WS + i];
        v *= (1.0f/49.0f);
        v = v > 0.f ? v : 0.01f*v;          // leaky_relu(0.01)
        g_act[(b*CC + c)*NWIN + wy*WN + tid] = v;
    }
}

// ---------------------------------------------------------------------------
// Kernel 2: tiny GEMMs for offset/scale -> g_par per (b, head, window)
// ---------------------------------------------------------------------------
__global__ __launch_bounds__(128) void k_offscl(const float* __restrict__ w_off,
                                                const float* __restrict__ b_off,
                                                const float* __restrict__ w_scl,
                                                const float* __restrict__ b_scl) {
    int pos = blockIdx.x, b = blockIdx.y, tid = threadIdx.x;
    __shared__ float a[CC];
    if (tid < CC) a[tid] = g_act[(b*CC + tid)*NWIN + pos];
    __syncthreads();
    if (tid < 12) {
        bool is_scl = (tid >= 6);
        int o = is_scl ? tid - 6 : tid;
        const float* w = is_scl ? w_scl : w_off;
        float acc = is_scl ? b_scl[o] : b_off[o];
        for (int c = 0; c < CC; c++) acc += w[o*CC + c]*a[c];
        int head = o >> 1, axis = o & 1;
        int base = ((b*HEADS + head)*NWIN + pos)*4;
        if (is_scl) g_par[base + axis]     = acc;               // sclx / scly
        else        g_par[base + 2 + axis] = acc * (55.5f/16.0f); // px-unit offset
    }
}

// ---------------------------------------------------------------------------
// Kernel 3: qkv 1x1 conv GEMM. out[o][pix] = sum_c W[o][c]*x[c][pix] + bias
// grid(98, 3, 16) block 256; tile = 128 pixels x 96 outputs, K chunks of 16
// ---------------------------------------------------------------------------
__global__ __launch_bounds__(256) void k_qkv(const float* __restrict__ x,
                                             const float* __restrict__ w_qkv,
                                             const float* __restrict__ b_qkv) {
    int pix0 = blockIdx.x*128;
    int which = blockIdx.y;
    int b = blockIdx.z;
    float* out = (which == 0) ? g_q : (which == 1) ? g_k : g_v;

    __shared__ float xs[16][128];
    __shared__ float ws[16][96];

    int t = threadIdx.x;
    int pp = t & 15, po = t >> 4;

    float acc[6][8];
    #pragma unroll
    for (int i = 0; i < 6; i++) {
        float bb = b_qkv[which*96 + po + i*16];
        #pragma unroll
        for (int j = 0; j < 8; j++) acc[i][j] = bb;
    }

    for (int kc = 0; kc < 6; kc++) {
        for (int idx = t; idx < 16*96; idx += 256) {
            int kk = idx/96, o = idx - kk*96;
            ws[kk][o] = w_qkv[(which*96 + o)*96 + kc*16 + kk];
        }
        for (int idx = t; idx < 16*128; idx += 256) {
            int kk = idx >> 7, p = idx & 127;
            xs[kk][p] = x[(b*CC + kc*16 + kk)*NPIX + pix0 + p];
        }
        __syncthreads();
        #pragma unroll
        for (int kk = 0; kk < 16; kk++) {
            float xv[8];
            #pragma unroll
            for (int j = 0; j < 8; j++) xv[j] = xs[kk][pp + j*16];
            #pragma unroll
            for (int i = 0; i < 6; i++) {
                float wv = ws[kk][po + i*16];
                #pragma unroll
                for (int j = 0; j < 8; j++) acc[i][j] += wv*xv[j];
            }
        }
        __syncthreads();
    }
    #pragma unroll
    for (int i = 0; i < 6; i++)
        #pragma unroll
        for (int j = 0; j < 8; j++)
            out[(b*CC + po + i*16)*NPIX + pix0 + pp + j*16] = acc[i][j];
}

// ---------------------------------------------------------------------------
// Kernel 4: per-window deformable sampling + attention
// grid(256, 3, 16), block 128
// ---------------------------------------------------------------------------
__global__ __launch_bounds__(128) void k_attn(const float* __restrict__ rpb) {
    int wpos = blockIdx.x, head = blockIdx.y, b = blockIdx.z;
    int wy = wpos >> 4, wx = wpos & 15;
    int bh = b*HEADS + head;
    int tid = threadIdx.x;
    int y0 = wy*WS, x0 = wx*WS;

    __shared__ float qs[49*33];
    __shared__ float ks[49*33];
    __shared__ float vs[49*33];
    __shared__ float att[49*49];
    __shared__ float rpbs[169];
    __shared__ int   sx0[7], sy0[7];
    __shared__ float sfx[7], sfy[7];

    const float* par = g_par + (bh*NWIN + wpos)*4;
    float sclx = par[0], scly = par[1], ox = par[2], oy = par[3];

    if (tid < 7) {
        float px = (float)(x0 + tid) + (float)(tid - 3)*sclx + ox;
        float f = floorf(px);
        sx0[tid] = (int)f; sfx[tid] = px - f;
    } else if (tid < 14) {
        int r = tid - 7;
        float py = (float)(y0 + r) + (float)(r - 3)*scly + oy;
        float f = floorf(py);
        sy0[r] = (int)f; sfy[r] = py - f;
    }
    for (int i = tid; i < 169; i += 128) rpbs[i] = rpb[i*HEADS + head];

    // q load (pre-multiplied by softmax scale)
    const float* qbase = g_q + (b*CC + head*DH)*NPIX;
    for (int idx = tid; idx < 49*DH; idx += 128) {
        int d = idx/49, j = idx - d*49;
        int r = j/7, s = j - r*7;
        qs[j*33 + d] = qbase[d*NPIX + (y0 + r)*WW + x0 + s] * SCALE;
    }
    __syncthreads();

    // bilinear sampling of k, v (zeros padding)
    const float* kbase = g_k + (b*CC + head*DH)*NPIX;
    const float* vbase = g_v + (b*CC + head*DH)*NPIX;
    for (int idx = tid; idx < 49*DH; idx += 128) {
        int d = idx/49, j = idx - d*49;
        int r = j/7, s = j - r*7;
        int ix0 = sx0[s], iy0 = sy0[r];
        float tx = sfx[s], ty = sfy[r];
        int ix1 = ix0 + 1, iy1 = iy0 + 1;
        float vx0 = (ix0 >= 0 && ix0 < WW) ? 1.f : 0.f;
        float vx1 = (ix1 >= 0 && ix1 < WW) ? 1.f : 0.f;
        float vy0 = (iy0 >= 0 && iy0 < HH) ? 1.f : 0.f;
        float vy1 = (iy1 >= 0 && iy1 < HH) ? 1.f : 0.f;
        int jx0 = min(max(ix0,0),WW-1), jx1 = min(max(ix1,0),WW-1);
        int jy0 = min(max(iy0,0),HH-1), jy1 = min(max(iy1,0),HH-1);
        float w00 = (1.f-tx)*(1.f-ty)*vx0*vy0;
        float w10 = tx*(1.f-ty)*vx1*vy0;
        float w01 = (1.f-tx)*ty*vx0*vy1;
        float w11 = tx*ty*vx1*vy1;
        const float* kp = kbase + d*NPIX;
        ks[j*33 + d] = w00*kp[jy0*WW + jx0] + w10*kp[jy0*WW + jx1]
                     + w01*kp[jy1*WW + jx0] + w11*kp[jy1*WW + jx1];
        const float* vp = vbase + d*NPIX;
        vs[j*33 + d] = w00*vp[jy0*WW + jx0] + w10*vp[jy0*WW + jx1]
                     + w01*vp[jy1*WW + jx0] + w11*vp[jy1*WW + jx1];
    }
    __syncthreads();

    // dots = q @ k^T + bias, 4x4 register tiling over (qi, ki). 13x13 tiles.
    for (int t2 = tid; t2 < 13*13; t2 += 128) {
        int ti = t2/13, tk = t2 - ti*13;
        int q0 = ti*4, k0 = tk*4;
        float acc[4][4];
        #pragma unroll
        for (int i = 0; i < 4; i++)
            #pragma unroll
            for (int j = 0; j < 4; j++) acc[i][j] = 0.f;
        #pragma unroll
        for (int d = 0; d < DH; d++) {
            float qv[4], kv[4];
            #pragma unroll
            for (int i = 0; i < 4; i++) qv[i] = qs[min(q0+i,48)*33 + d];
            #pragma unroll
            for (int j = 0; j < 4; j++) kv[j] = ks[min(k0+j,48)*33 + d];
            #pragma unroll
            for (int i = 0; i < 4; i++)
                #pragma unroll
                for (int j = 0; j < 4; j++) acc[i][j] += qv[i]*kv[j];
        }
        #pragma unroll
        for (int i = 0; i < 4; i++) {
            int qi = q0 + i; if (qi >= 49) break;
            int qr = qi/7, qsx = qi - qr*7;
            #pragma unroll
            for (int j = 0; j < 4; j++) {
                int ki = k0 + j; if (ki >= 49) continue;
                int kr = ki/7, ksx = ki - kr*7;
                int bidx = (qr - kr + 6)*13 + (qsx - ksx + 6);
                att[qi*49 + ki] = acc[i][j] + rpbs[bidx];
            }
        }
    }
    __syncthreads();

    // softmax rows
    if (tid < 49) {
        float m = -1e30f;
        for (int k2 = 0; k2 < 49; k2++) m = fmaxf(m, att[tid*49 + k2]);
        float sum = 0.f;
        for (int k2 = 0; k2 < 49; k2++) {
            float e = __expf(att[tid*49 + k2] - m);
            att[tid*49 + k2] = e;
            sum += e;
        }
        float inv = 1.f/sum;
        for (int k2 = 0; k2 < 49; k2++) att[tid*49 + k2] *= inv;
    }
    __syncthreads();

    // out = attn @ v, 4x4 tiling over (j, d). 13 j-tiles x 8 d-tiles.
    float* obase = g_ao + (b*CC + head*DH)*NPIX;
    for (int t2 = tid; t2 < 13*8; t2 += 128) {
        int jt = t2/8, dt = t2 - jt*8;
        int j0 = jt*4, d0 = dt*4;
        float acc[4][4];
        #pragma unroll
        for (int i = 0; i < 4; i++)
            #pragma unroll
            for (int j = 0; j < 4; j++) acc[i][j] = 0.f;
        for (int ki = 0; ki < 49; ki++) {
            float av[4], vv[4];
            #pragma unroll
            for (int i = 0; i < 4; i++) av[i] = att[min(j0+i,48)*49 + ki];
            #pragma unroll
            for (int j = 0; j < 4; j++) vv[j] = vs[ki*33 + d0 + j];
            #pragma unroll
            for (int i = 0; i < 4; i++)
                #pragma unroll
                for (int j = 0; j < 4; j++) acc[i][j] += av[i]*vv[j];
        }
        #pragma unroll
        for (int i = 0; i < 4; i++) {
            int j = j0 + i; if (j >= 49) break;
            int r = j/7, s = j - r*7;
            #pragma unroll
            for (int jj = 0; jj < 4; jj++)
                obase[(d0 + jj)*NPIX + (y0 + r)*WW + x0 + s] = acc[i][jj];
        }
    }
}

// ---------------------------------------------------------------------------
// Kernel 5: output projection GEMM (+bias) -> d_out
// grid(98, 16) block 256
// ---------------------------------------------------------------------------
__global__ __launch_bounds__(256) void k_proj(const float* __restrict__ w_proj,
                                              const float* __restrict__ b_proj,
                                              float* __restrict__ out) {
    int pix0 = blockIdx.x*128;
    int b = blockIdx.y;

    __shared__ float xs[16][128];
    __shared__ float ws[16][96];

    int t = threadIdx.x;
    int pp = t & 15, po = t >> 4;

    float acc[6][8];
    #pragma unroll
    for (int i = 0; i < 6; i++) {
        float bb = b_proj[po + i*16];
        #pragma unroll
        for (int j = 0; j < 8; j++) acc[i][j] = bb;
    }

    for (int kc = 0; kc < 6; kc++) {
        for (int idx = t; idx < 16*96; idx += 256) {
            int kk = idx/96, o = idx - kk*96;
            ws[kk][o] = w_proj[o*96 + kc*16 + kk];
        }
        for (int idx = t; idx < 16*128; idx += 256) {
            int kk = idx >> 7, p = idx & 127;
            xs[kk][p] = g_ao[(b*CC + kc*16 + kk)*NPIX + pix0 + p];
        }
        __syncthreads();
        #pragma unroll
        for (int kk = 0; kk < 16; kk++) {
            float xv[8];
            #pragma unroll
            for (int j = 0; j < 8; j++) xv[j] = xs[kk][pp + j*16];
            #pragma unroll
            for (int i = 0; i < 6; i++) {
                float wv = ws[kk][po + i*16];
                #pragma unroll
                for (int j = 0; j < 8; j++) acc[i][j] += wv*xv[j];
            }
        }
        __syncthreads();
    }
    #pragma unroll
    for (int i = 0; i < 6; i++)
        #pragma unroll
        for (int j = 0; j < 8; j++)
            out[(b*CC + po + i*16)*NPIX + pix0 + pp + j*16] = acc[i][j];
}

// ---------------------------------------------------------------------------
extern "C" void kernel_launch(void* const* d_in, const int* in_sizes, int n_in,
                              void* d_out, int out_size) {
    const float* x      = (const float*)d_in[0];
    const float* w_qkv  = (const float*)d_in[1];
    const float* b_qkv  = (const float*)d_in[2];
    const float* w_off  = (const float*)d_in[3];
    const float* b_off  = (const float*)d_in[4];
    const float* w_scl  = (const float*)d_in[5];
    const float* b_scl  = (const float*)d_in[6];
    const float* rpb    = (const float*)d_in[7];
    const float* w_proj = (const float*)d_in[8];
    const float* b_proj = (const float*)d_in[9];
    float* out = (float*)d_out;

    k_pool  <<<dim3(WN, CC, BB), 128>>>(x);
    k_offscl<<<dim3(NWIN, BB), 128>>>(w_off, b_off, w_scl, b_scl);
    k_qkv   <<<dim3(NPIX/128, 3, BB), 256>>>(x, w_qkv, b_qkv);
    k_attn  <<<dim3(NWIN, HEADS, BB), 128>>>(rpb);
    k_proj  <<<dim3(NPIX/128, BB), 256>>>(w_proj, b_proj, out);
}

// round 3
// speedup vs baseline: 1.2723x; 1.2723x over previous
#include <cuda_runtime.h>
#include <cuda_bf16.h>

// Problem constants
#define BB    16
#define CC    96
#define HH    112
#define WW    112
#define NPIX  (HH*WW)        // 12544
#define WS    7
#define WN    16             // windows per dim
#define HEADS 3
#define DH    32
#define NWIN  (WN*WN)        // 256 windows per image
#define SCALE 0.17677669529663689f   // 32^-0.5

// Scratch (static device globals; allocation-free at launch time)
__device__ float g_q [BB*CC*NPIX];
__device__ float g_k [BB*CC*NPIX];
__device__ float g_v [BB*CC*NPIX];
__device__ float g_ao[BB*CC*NPIX];
__device__ float g_act[BB*CC*NWIN];
__device__ float g_par[BB*HEADS*NWIN*4];   // sclx, scly, ox(px units), oy(px units)

// ---- packed fp32x2 helpers (Blackwell FFMA2 via PTX) ----------------------
__device__ __forceinline__ unsigned long long pk2(float lo, float hi) {
    unsigned long long r;
    asm("mov.b64 %0,{%1,%2};" : "=l"(r) : "f"(lo), "f"(hi));
    return r;
}
__device__ __forceinline__ void fma2(unsigned long long& d,
                                     unsigned long long a, unsigned long long b) {
    asm("fma.rn.f32x2 %0,%1,%2,%0;" : "+l"(d) : "l"(a), "l"(b));
}
__device__ __forceinline__ void unpk2(unsigned long long v, float& lo, float& hi) {
    asm("mov.b64 {%0,%1},%2;" : "=f"(lo), "=f"(hi) : "l"(v));
}

// ---------------------------------------------------------------------------
// Kernel 1: 7x7 window mean pooling + leaky_relu -> g_act[b][c][wy][wx]
// ---------------------------------------------------------------------------
__global__ __launch_bounds__(128) void k_pool(const float* __restrict__ x) {
    int wy = blockIdx.x, c = blockIdx.y, b = blockIdx.z;
    int tid = threadIdx.x;
    __shared__ float s[112];
    if (tid < 112) {
        const float* p = x + ((b*CC + c)*HH + wy*WS)*WW + tid;
        float v = 0.f;
        #pragma unroll
        for (int r = 0; r < WS; r++) v += p[r*WW];
        s[tid] = v;
    }
    __syncthreads();
    if (tid < WN) {
        float v = 0.f;
        #pragma unroll
        for (int i = 0; i < WS; i++) v += s[tid*WS + i];
        v *= (1.0f/49.0f);
        v = v > 0.f ? v : 0.01f*v;
        g_act[(b*CC + c)*NWIN + wy*WN + tid] = v;
    }
}

// ---------------------------------------------------------------------------
// Kernel 2: tiny GEMMs for offset/scale -> g_par per (b, head, window)
// ---------------------------------------------------------------------------
__global__ __launch_bounds__(128) void k_offscl(const float* __restrict__ w_off,
                                                const float* __restrict__ b_off,
                                                const float* __restrict__ w_scl,
                                                const float* __restrict__ b_scl) {
    int pos = blockIdx.x, b = blockIdx.y, tid = threadIdx.x;
    __shared__ float a[CC];
    if (tid < CC) a[tid] = g_act[(b*CC + tid)*NWIN + pos];
    __syncthreads();
    if (tid < 12) {
        bool is_scl = (tid >= 6);
        int o = is_scl ? tid - 6 : tid;
        const float* w = is_scl ? w_scl : w_off;
        float acc = is_scl ? b_scl[o] : b_off[o];
        for (int c = 0; c < CC; c++) acc += w[o*CC + c]*a[c];
        int head = o >> 1, axis = o & 1;
        int base = ((b*HEADS + head)*NWIN + pos)*4;
        if (is_scl) g_par[base + axis]     = acc;                  // sclx / scly
        else        g_par[base + 2 + axis] = acc * (55.5f/16.0f);  // px-unit offset
    }
}

// ---------------------------------------------------------------------------
// Kernel 3: qkv 1x1-conv GEMM, 128 thr, tile 96 out x 128 pix, 12x8 reg tile
// ---------------------------------------------------------------------------
__global__ __launch_bounds__(128) void k_qkv(const float* __restrict__ x,
                                             const float* __restrict__ w_qkv,
                                             const float* __restrict__ b_qkv) {
    int pix0 = blockIdx.x*128;
    int which = blockIdx.y;
    int b = blockIdx.z;
    float* out = (which == 0) ? g_q : (which == 1) ? g_k : g_v;

    __shared__ __align__(16) float xs[16][128];
    __shared__ __align__(16) float ws[16][100];   // pad 100: 16B-aligned rows

    int t = threadIdx.x;
    int pg = t & 15;      // 8 contiguous pixels: pix0 + pg*8 ..
    int og = t >> 4;      // 12 outputs: og*12 ..

    unsigned long long acc[12][4];
    #pragma unroll
    for (int i = 0; i < 12; i++) {
        float bb = b_qkv[which*96 + og*12 + i];
        unsigned long long p = pk2(bb, bb);
        #pragma unroll
        for (int j = 0; j < 4; j++) acc[i][j] = p;
    }

    for (int kc = 0; kc < 6; kc++) {
        // weights: 96 o x 16 k, transposed into ws[kk][o]
        #pragma unroll
        for (int it = 0; it < 12; it++) {
            int idx = t + it*128;
            int o = idx >> 4, kk = idx & 15;
            ws[kk][o] = w_qkv[(which*96 + o)*96 + kc*16 + kk];
        }
        // x: 16 rows x 128 pixels, float4
        #pragma unroll
        for (int it = 0; it < 4; it++) {
            int idx4 = t + it*128;
            int kk = idx4 >> 5, p4 = idx4 & 31;
            *(float4*)&xs[kk][p4*4] =
                *(const float4*)&x[(b*CC + kc*16 + kk)*NPIX + pix0 + p4*4];
        }
        __syncthreads();
        #pragma unroll 4
        for (int kk = 0; kk < 16; kk++) {
            float4 xa = *(float4*)&xs[kk][pg*8];
            float4 xb = *(float4*)&xs[kk][pg*8 + 4];
            unsigned long long xv[4] = { pk2(xa.x, xa.y), pk2(xa.z, xa.w),
                                         pk2(xb.x, xb.y), pk2(xb.z, xb.w) };
            float4 w0 = *(float4*)&ws[kk][og*12];
            float4 w1 = *(float4*)&ws[kk][og*12 + 4];
            float4 w2 = *(float4*)&ws[kk][og*12 + 8];
            float wv[12] = { w0.x,w0.y,w0.z,w0.w, w1.x,w1.y,w1.z,w1.w,
                             w2.x,w2.y,w2.z,w2.w };
            #pragma unroll
            for (int i = 0; i < 12; i++) {
                unsigned long long wd = pk2(wv[i], wv[i]);
                #pragma unroll
                for (int j = 0; j < 4; j++) fma2(acc[i][j], wd, xv[j]);
            }
        }
        __syncthreads();
    }
    #pragma unroll
    for (int i = 0; i < 12; i++) {
        float f[8];
        #pragma unroll
        for (int j = 0; j < 4; j++) unpk2(acc[i][j], f[2*j], f[2*j+1]);
        float* op = out + (b*CC + og*12 + i)*NPIX + pix0 + pg*8;
        *(float4*)op       = make_float4(f[0], f[1], f[2], f[3]);
        *(float4*)(op + 4) = make_float4(f[4], f[5], f[6], f[7]);
    }
}

// ---------------------------------------------------------------------------
// Kernel 4: per-window deformable sampling + attention
// layouts: qs/ks [d][j] (pad 52), vs [j][d] (pad 36), at [k][q] (pad 52)
// ---------------------------------------------------------------------------
__global__ __launch_bounds__(128) void k_attn(const float* __restrict__ rpb) {
    int wpos = blockIdx.x, head = blockIdx.y, b = blockIdx.z;
    int wy = wpos >> 4, wx = wpos & 15;
    int tid = threadIdx.x;
    int y0 = wy*WS, x0 = wx*WS;

    __shared__ __align__(16) float qs[32*52];
    __shared__ __align__(16) float ks[32*52];
    __shared__ __align__(16) float vs[49*36];
    __shared__ __align__(16) float at[49*52];
    __shared__ float rpbs[169];
    __shared__ float4 swt[49];
    __shared__ int4  sidx[49];

    const float* par = g_par + ((b*HEADS + head)*NWIN + wpos)*4;
    float sclx = par[0], scly = par[1], ox = par[2], oy = par[3];

    // per-j bilinear tables
    if (tid < 49) {
        int r = tid/7, s = tid - r*7;
        float px = (float)(x0 + s) + (float)(s - 3)*sclx + ox;
        float py = (float)(y0 + r) + (float)(r - 3)*scly + oy;
        float fx = floorf(px), fy = floorf(py);
        int ix0 = (int)fx, iy0 = (int)fy;
        float tx = px - fx, ty = py - fy;
        int ix1 = ix0 + 1, iy1 = iy0 + 1;
        float vx0 = (ix0 >= 0 && ix0 < WW) ? 1.f : 0.f;
        float vx1 = (ix1 >= 0 && ix1 < WW) ? 1.f : 0.f;
        float vy0 = (iy0 >= 0 && iy0 < HH) ? 1.f : 0.f;
        float vy1 = (iy1 >= 0 && iy1 < HH) ? 1.f : 0.f;
        int jx0 = min(max(ix0,0),WW-1), jx1 = min(max(ix1,0),WW-1);
        int jy0 = min(max(iy0,0),HH-1), jy1 = min(max(iy1,0),HH-1);
        swt[tid]  = make_float4((1.f-tx)*(1.f-ty)*vx0*vy0, tx*(1.f-ty)*vx1*vy0,
                                (1.f-tx)*ty*vx0*vy1,       tx*ty*vx1*vy1);
        sidx[tid] = make_int4(jy0*WW + jx0, jy0*WW + jx1,
                              jy1*WW + jx0, jy1*WW + jx1);
    }
    for (int i = tid; i < 169; i += 128) rpbs[i] = rpb[i*HEADS + head];
    __syncthreads();

    // load q (scaled), sample k/v
    const float* qbase = g_q + (b*CC + head*DH)*NPIX;
    const float* kbase = g_k + (b*CC + head*DH)*NPIX;
    const float* vbase = g_v + (b*CC + head*DH)*NPIX;
    for (int idx = tid; idx < 49*DH; idx += 128) {
        int d = idx/49, j = idx - d*49;
        int r = j/7, s = j - r*7;
        int pix = (y0 + r)*WW + x0 + s;
        qs[d*52 + j] = qbase[d*NPIX + pix]*SCALE;
        float4 w4 = swt[j];
        int4  i4 = sidx[j];
        const float* kp = kbase + d*NPIX;
        ks[d*52 + j] = w4.x*kp[i4.x] + w4.y*kp[i4.y] + w4.z*kp[i4.z] + w4.w*kp[i4.w];
        const float* vp = vbase + d*NPIX;
        vs[j*36 + d] = w4.x*vp[i4.x] + w4.y*vp[i4.y] + w4.z*vp[i4.z] + w4.w*vp[i4.w];
    }
    __syncthreads();

    // dots = q @ k^T + bias -> at[k][q] (transposed)
    for (int t2 = tid; t2 < 169; t2 += 128) {
        int ti = t2/13, tk = t2 - ti*13;
        int q0 = ti*4, k0 = tk*4;
        unsigned long long acc[4][2] = {{0,0},{0,0},{0,0},{0,0}};
        #pragma unroll 8
        for (int d = 0; d < DH; d++) {
            float4 qv = *(float4*)&qs[d*52 + q0];
            float4 kv = *(float4*)&ks[d*52 + k0];
            unsigned long long kA = pk2(kv.x, kv.y), kB = pk2(kv.z, kv.w);
            unsigned long long qd;
            qd = pk2(qv.x, qv.x); fma2(acc[0][0], qd, kA); fma2(acc[0][1], qd, kB);
            qd = pk2(qv.y, qv.y); fma2(acc[1][0], qd, kA); fma2(acc[1][1], qd, kB);
            qd = pk2(qv.z, qv.z); fma2(acc[2][0], qd, kA); fma2(acc[2][1], qd, kB);
            qd = pk2(qv.w, qv.w); fma2(acc[3][0], qd, kA); fma2(acc[3][1], qd, kB);
        }
        #pragma unroll
        for (int i = 0; i < 4; i++) {
            int qi = q0 + i; if (qi >= 49) break;
            int qr = qi/7, qsx = qi - qr*7;
            #pragma unroll
            for (int jp = 0; jp < 2; jp++) {
                float f0, f1; unpk2(acc[i][jp], f0, f1);
                int ki = k0 + jp*2;
                if (ki <= 48) {
                    int kr = ki/7, ksx = ki - kr*7;
                    at[ki*52 + qi] = f0 + rpbs[(qr - kr + 6)*13 + (qsx - ksx + 6)];
                }
                ki++;
                if (ki <= 48) {
                    int kr = ki/7, ksx = ki - kr*7;
                    at[ki*52 + qi] = f1 + rpbs[(qr - kr + 6)*13 + (qsx - ksx + 6)];
                }
            }
        }
    }
    __syncthreads();

    // softmax over k for each q (column q of at)
    if (tid < 49) {
        float m = -1e30f;
        for (int k2 = 0; k2 < 49; k2++) m = fmaxf(m, at[k2*52 + tid]);
        float sum = 0.f;
        for (int k2 = 0; k2 < 49; k2++) {
            float e = __expf(at[k2*52 + tid] - m);
            at[k2*52 + tid] = e;
            sum += e;
        }
        float inv = 1.f/sum;
        for (int k2 = 0; k2 < 49; k2++) at[k2*52 + tid] *= inv;
    }
    __syncthreads();

    // out = attn @ v : tiles 4 q x 4 d, both operands float4
    float* obase = g_ao + (b*CC + head*DH)*NPIX;
    for (int t2 = tid; t2 < 104; t2 += 128) {
        int jt = t2 >> 3, dt = t2 & 7;
        int j0 = jt*4, d0 = dt*4;
        unsigned long long acc[4][2] = {{0,0},{0,0},{0,0},{0,0}};
        #pragma unroll 7
        for (int ki = 0; ki < 49; ki++) {
            float4 av = *(float4*)&at[ki*52 + j0];
            float4 vv = *(float4*)&vs[ki*36 + d0];
            unsigned long long vA = pk2(vv.x, vv.y), vB = pk2(vv.z, vv.w);
            unsigned long long ad;
            ad = pk2(av.x, av.x); fma2(acc[0][0], ad, vA); fma2(acc[0][1], ad, vB);
            ad = pk2(av.y, av.y); fma2(acc[1][0], ad, vA); fma2(acc[1][1], ad, vB);
            ad = pk2(av.z, av.z); fma2(acc[2][0], ad, vA); fma2(acc[2][1], ad, vB);
            ad = pk2(av.w, av.w); fma2(acc[3][0], ad, vA); fma2(acc[3][1], ad, vB);
        }
        #pragma unroll
        for (int i = 0; i < 4; i++) {
            int j = j0 + i; if (j >= 49) break;
            int r = j/7, s = j - r*7;
            int pix = (y0 + r)*WW + x0 + s;
            float f0, f1, f2, f3;
            unpk2(acc[i][0], f0, f1);
            unpk2(acc[i][1], f2, f3);
            obase[(d0+0)*NPIX + pix] = f0;
            obase[(d0+1)*NPIX + pix] = f1;
            obase[(d0+2)*NPIX + pix] = f2;
            obase[(d0+3)*NPIX + pix] = f3;
        }
    }
}

// ---------------------------------------------------------------------------
// Kernel 5: output projection GEMM (+bias) -> d_out. Same tiling as k_qkv.
// ---------------------------------------------------------------------------
__global__ __launch_bounds__(128) void k_proj(const float* __restrict__ w_proj,
                                              const float* __restrict__ b_proj,
                                              float* __restrict__ out) {
    int pix0 = blockIdx.x*128;
    int b = blockIdx.y;

    __shared__ __align__(16) float xs[16][128];
    __shared__ __align__(16) float ws[16][100];

    int t = threadIdx.x;
    int pg = t & 15;
    int og = t >> 4;

    unsigned long long acc[12][4];
    #pragma unroll
    for (int i = 0; i < 12; i++) {
        float bb = b_proj[og*12 + i];
        unsigned long long p = pk2(bb, bb);
        #pragma unroll
        for (int j = 0; j < 4; j++) acc[i][j] = p;
    }

    for (int kc = 0; kc < 6; kc++) {
        #pragma unroll
        for (int it = 0; it < 12; it++) {
            int idx = t + it*128;
            int o = idx >> 4, kk = idx & 15;
            ws[kk][o] = w_proj[o*96 + kc*16 + kk];
        }
        #pragma unroll
        for (int it = 0; it < 4; it++) {
            int idx4 = t + it*128;
            int kk = idx4 >> 5, p4 = idx4 & 31;
            *(float4*)&xs[kk][p4*4] =
                *(const float4*)&g_ao[(b*CC + kc*16 + kk)*NPIX + pix0 + p4*4];
        }
        __syncthreads();
        #pragma unroll 4
        for (int kk = 0; kk < 16; kk++) {
            float4 xa = *(float4*)&xs[kk][pg*8];
            float4 xb = *(float4*)&xs[kk][pg*8 + 4];
            unsigned long long xv[4] = { pk2(xa.x, xa.y), pk2(xa.z, xa.w),
                                         pk2(xb.x, xb.y), pk2(xb.z, xb.w) };
            float4 w0 = *(float4*)&ws[kk][og*12];
            float4 w1 = *(float4*)&ws[kk][og*12 + 4];
            float4 w2 = *(float4*)&ws[kk][og*12 + 8];
            float wv[12] = { w0.x,w0.y,w0.z,w0.w, w1.x,w1.y,w1.z,w1.w,
                             w2.x,w2.y,w2.z,w2.w };
            #pragma unroll
            for (int i = 0; i < 12; i++) {
                unsigned long long wd = pk2(wv[i], wv[i]);
                #pragma unroll
                for (int j = 0; j < 4; j++) fma2(acc[i][j], wd, xv[j]);
            }
        }
        __syncthreads();
    }
    #pragma unroll
    for (int i = 0; i < 12; i++) {
        float f[8];
        #pragma unroll
        for (int j = 0; j < 4; j++) unpk2(acc[i][j], f[2*j], f[2*j+1]);
        float* op = out + (b*CC + og*12 + i)*NPIX + pix0 + pg*8;
        *(float4*)op       = make_float4(f[0], f[1], f[2], f[3]);
        *(float4*)(op + 4) = make_float4(f[4], f[5], f[6], f[7]);
    }
}

// ---------------------------------------------------------------------------
extern "C" void kernel_launch(void* const* d_in, const int* in_sizes, int n_in,
                              void* d_out, int out_size) {
    const float* x      = (const float*)d_in[0];
    const float* w_qkv  = (const float*)d_in[1];
    const float* b_qkv  = (const float*)d_in[2];
    const float* w_off  = (const float*)d_in[3];
    const float* b_off  = (const float*)d_in[4];
    const float* w_scl  = (const float*)d_in[5];
    const float* b_scl  = (const float*)d_in[6];
    const float* rpb    = (const float*)d_in[7];
    const float* w_proj = (const float*)d_in[8];
    const float* b_proj = (const float*)d_in[9];
    float* out = (float*)d_out;

    k_pool  <<<dim3(WN, CC, BB), 128>>>(x);
    k_offscl<<<dim3(NWIN, BB), 128>>>(w_off, b_off, w_scl, b_scl);
    k_qkv   <<<dim3(NPIX/128, 3, BB), 128>>>(x, w_qkv, b_qkv);
    k_attn  <<<dim3(NWIN, HEADS, BB), 128>>>(rpb);
    k_proj  <<<dim3(NPIX/128, BB), 128>>>(w_proj, b_proj, out);
}

// round 16
// speedup vs baseline: 1.5506x; 1.2188x over previous
#include <cuda_runtime.h>
#include <cuda_bf16.h>

// Problem constants
#define BB    16
#define CC    96
#define HH    112
#define WW    112
#define NPIX  (HH*WW)        // 12544
#define WS    7
#define WN    16             // windows per dim
#define HEADS 3
#define DH    32
#define NWIN  (WN*WN)        // 256 windows per image
#define SCALE 0.17677669529663689f   // 32^-0.5

// Scratch. q/k/v/ao are CHANNEL-CONTIGUOUS: [b][pix][96] (pixel record 384B,
// each head's 32-ch slice = exactly one aligned 128B line).
__device__ float g_q [BB*NPIX*CC];
__device__ float g_k [BB*NPIX*CC];
__device__ float g_v [BB*NPIX*CC];
__device__ float g_ao[BB*NPIX*CC];
__device__ float g_act[BB*CC*NWIN];
__device__ float g_par[BB*HEADS*NWIN*4];   // sclx, scly, ox(px), oy(px)

// ---- packed fp32x2 helpers (Blackwell FFMA2 via PTX) ----------------------
__device__ __forceinline__ unsigned long long pk2(float lo, float hi) {
    unsigned long long r;
    asm("mov.b64 %0,{%1,%2};" : "=l"(r) : "f"(lo), "f"(hi));
    return r;
}
__device__ __forceinline__ void fma2(unsigned long long& d,
                                     unsigned long long a, unsigned long long b) {
    asm("fma.rn.f32x2 %0,%1,%2,%0;" : "+l"(d) : "l"(a), "l"(b));
}
__device__ __forceinline__ void unpk2(unsigned long long v, float& lo, float& hi) {
    asm("mov.b64 {%0,%1},%2;" : "=f"(lo), "=f"(hi) : "l"(v));
}

// ---------------------------------------------------------------------------
// Kernel 1: 7x7 window mean pooling + leaky_relu -> g_act[b][c][wy][wx]
// ---------------------------------------------------------------------------
__global__ __launch_bounds__(128) void k_pool(const float* __restrict__ x) {
    int wy = blockIdx.x, c = blockIdx.y, b = blockIdx.z;
    int tid = threadIdx.x;
    __shared__ float s[112];
    if (tid < 112) {
        const float* p = x + ((b*CC + c)*HH + wy*WS)*WW + tid;
        float v = 0.f;
        #pragma unroll
        for (int r = 0; r < WS; r++) v += p[r*WW];
        s[tid] = v;
    }
    __syncthreads();
    if (tid < WN) {
        float v = 0.f;
        #pragma unroll
        for (int i = 0; i < WS; i++) v += s[tid*WS + i];
        v *= (1.0f/49.0f);
        v = v > 0.f ? v : 0.01f*v;
        g_act[(b*CC + c)*NWIN + wy*WN + tid] = v;
    }
}

// ---------------------------------------------------------------------------
// Kernel 2: tiny GEMMs for offset/scale -> g_par per (b, head, window)
// ---------------------------------------------------------------------------
__global__ __launch_bounds__(128) void k_offscl(const float* __restrict__ w_off,
                                                const float* __restrict__ b_off,
                                                const float* __restrict__ w_scl,
                                                const float* __restrict__ b_scl) {
    int pos = blockIdx.x, b = blockIdx.y, tid = threadIdx.x;
    __shared__ float a[CC];
    if (tid < CC) a[tid] = g_act[(b*CC + tid)*NWIN + pos];
    __syncthreads();
    if (tid < 12) {
        bool is_scl = (tid >= 6);
        int o = is_scl ? tid - 6 : tid;
        const float* w = is_scl ? w_scl : w_off;
        float acc = is_scl ? b_scl[o] : b_off[o];
        for (int c = 0; c < CC; c++) acc += w[o*CC + c]*a[c];
        int head = o >> 1, axis = o & 1;
        int base = ((b*HEADS + head)*NWIN + pos)*4;
        if (is_scl) g_par[base + axis]     = acc;                  // sclx / scly
        else        g_par[base + 2 + axis] = acc * (55.5f/16.0f);  // px-unit offset
    }
}

// ---------------------------------------------------------------------------
// Kernel 3: qkv GEMM -> q/k/v in [pix][96] layout
// ---------------------------------------------------------------------------
__global__ __launch_bounds__(128) void k_qkv(const float* __restrict__ x,
                                             const float* __restrict__ w_qkv,
                                             const float* __restrict__ b_qkv) {
    int pix0 = blockIdx.x*128;
    int which = blockIdx.y;
    int b = blockIdx.z;
    float* out = (which == 0) ? g_q : (which == 1) ? g_k : g_v;

    __shared__ __align__(16) float xs[16][128];
    __shared__ __align__(16) float ws[16][100];

    int t = threadIdx.x;
    int pg = t & 15;      // 8 contiguous pixels: pix0 + pg*8 ..
    int og = t >> 4;      // 12 outputs: og*12 ..

    unsigned long long acc[12][4];
    #pragma unroll
    for (int i = 0; i < 12; i++) {
        float bb = b_qkv[which*96 + og*12 + i];
        unsigned long long p = pk2(bb, bb);
        #pragma unroll
        for (int j = 0; j < 4; j++) acc[i][j] = p;
    }

    for (int kc = 0; kc < 6; kc++) {
        #pragma unroll
        for (int it = 0; it < 12; it++) {
            int idx = t + it*128;
            int o = idx >> 4, kk = idx & 15;
            ws[kk][o] = w_qkv[(which*96 + o)*96 + kc*16 + kk];
        }
        #pragma unroll
        for (int it = 0; it < 4; it++) {
            int idx4 = t + it*128;
            int kk = idx4 >> 5, p4 = idx4 & 31;
            *(float4*)&xs[kk][p4*4] =
                *(const float4*)&x[(b*CC + kc*16 + kk)*NPIX + pix0 + p4*4];
        }
        __syncthreads();
        #pragma unroll 4
        for (int kk = 0; kk < 16; kk++) {
            float4 xa = *(float4*)&xs[kk][pg*8];
            float4 xb = *(float4*)&xs[kk][pg*8 + 4];
            unsigned long long xv[4] = { pk2(xa.x, xa.y), pk2(xa.z, xa.w),
                                         pk2(xb.x, xb.y), pk2(xb.z, xb.w) };
            float4 w0 = *(float4*)&ws[kk][og*12];
            float4 w1 = *(float4*)&ws[kk][og*12 + 4];
            float4 w2 = *(float4*)&ws[kk][og*12 + 8];
            float wv[12] = { w0.x,w0.y,w0.z,w0.w, w1.x,w1.y,w1.z,w1.w,
                             w2.x,w2.y,w2.z,w2.w };
            #pragma unroll
            for (int i = 0; i < 12; i++) {
                unsigned long long wd = pk2(wv[i], wv[i]);
                #pragma unroll
                for (int j = 0; j < 4; j++) fma2(acc[i][j], wd, xv[j]);
            }
        }
        __syncthreads();
    }
    // epilogue: per pixel, 12 contiguous channels -> 3 float4 stores
    #pragma unroll
    for (int j = 0; j < 4; j++) {
        float lo[12], hi[12];
        #pragma unroll
        for (int i = 0; i < 12; i++) unpk2(acc[i][j], lo[i], hi[i]);
        int p0 = pix0 + pg*8 + 2*j;
        float* o0 = out + (b*NPIX + p0)*96 + og*12;
        float* o1 = o0 + 96;
        *(float4*)(o0    ) = make_float4(lo[0], lo[1], lo[2], lo[3]);
        *(float4*)(o0 + 4) = make_float4(lo[4], lo[5], lo[6], lo[7]);
        *(float4*)(o0 + 8) = make_float4(lo[8], lo[9], lo[10], lo[11]);
        *(float4*)(o1    ) = make_float4(hi[0], hi[1], hi[2], hi[3]);
        *(float4*)(o1 + 4) = make_float4(hi[4], hi[5], hi[6], hi[7]);
        *(float4*)(o1 + 8) = make_float4(hi[8], hi[9], hi[10], hi[11]);
    }
}

// ---------------------------------------------------------------------------
// Kernel 4: per-window deformable sampling + attention
// q/k/v gathers are single-line LDG.128 per (pos, tap, 4ch)
// ---------------------------------------------------------------------------
__global__ __launch_bounds__(128) void k_attn(const float* __restrict__ rpb) {
    int wpos = blockIdx.x, head = blockIdx.y, b = blockIdx.z;
    int wy = wpos >> 4, wx = wpos & 15;
    int tid = threadIdx.x;
    int y0 = wy*WS, x0 = wx*WS;

    __shared__ __align__(16) float qs[32*52];   // [d][j]
    __shared__ __align__(16) float ks[32*52];   // [d][j]
    __shared__ __align__(16) float vs[49*36];   // [j][d]
    __shared__ __align__(16) float at[49*52];   // [k][q]
    __shared__ float rpbs[169];
    __shared__ float4 swt[49];
    __shared__ int4  sidx[49];

    const float* par = g_par + ((b*HEADS + head)*NWIN + wpos)*4;
    float sclx = par[0], scly = par[1], ox = par[2], oy = par[3];

    if (tid < 49) {
        int r = tid/7, s = tid - r*7;
        float px = (float)(x0 + s) + (float)(s - 3)*sclx + ox;
        float py = (float)(y0 + r) + (float)(r - 3)*scly + oy;
        float fx = floorf(px), fy = floorf(py);
        int ix0 = (int)fx, iy0 = (int)fy;
        float tx = px - fx, ty = py - fy;
        int ix1 = ix0 + 1, iy1 = iy0 + 1;
        float vx0 = (ix0 >= 0 && ix0 < WW) ? 1.f : 0.f;
        float vx1 = (ix1 >= 0 && ix1 < WW) ? 1.f : 0.f;
        float vy0 = (iy0 >= 0 && iy0 < HH) ? 1.f : 0.f;
        float vy1 = (iy1 >= 0 && iy1 < HH) ? 1.f : 0.f;
        int jx0 = min(max(ix0,0),WW-1), jx1 = min(max(ix1,0),WW-1);
        int jy0 = min(max(iy0,0),HH-1), jy1 = min(max(iy1,0),HH-1);
        swt[tid]  = make_float4((1.f-tx)*(1.f-ty)*vx0*vy0, tx*(1.f-ty)*vx1*vy0,
                                (1.f-tx)*ty*vx0*vy1,       tx*ty*vx1*vy1);
        sidx[tid] = make_int4(jy0*WW + jx0, jy0*WW + jx1,
                              jy1*WW + jx0, jy1*WW + jx1);
    }
    for (int i = tid; i < 169; i += 128) rpbs[i] = rpb[i*HEADS + head];
    __syncthreads();

    // sampling: idx = j*8 + c4 ; each chunk = 4 channels (float4)
    const float* qb = g_q + (size_t)b*NPIX*96;
    const float* kb = g_k + (size_t)b*NPIX*96;
    const float* vb = g_v + (size_t)b*NPIX*96;
    int chb = head*32;
    for (int idx = tid; idx < 49*8; idx += 128) {
        int j = idx >> 3, c4 = idx & 7;
        int r = j/7, s = j - r*7;
        int ch = chb + c4*4;
        int pw = (y0 + r)*WW + x0 + s;
        float4 qv = *(const float4*)&qb[pw*96 + ch];
        int d0 = c4*4;
        qs[(d0+0)*52 + j] = qv.x*SCALE;
        qs[(d0+1)*52 + j] = qv.y*SCALE;
        qs[(d0+2)*52 + j] = qv.z*SCALE;
        qs[(d0+3)*52 + j] = qv.w*SCALE;

        float4 w4 = swt[j];
        int4  i4 = sidx[j];
        float4 a0 = *(const float4*)&kb[i4.x*96 + ch];
        float4 a1 = *(const float4*)&kb[i4.y*96 + ch];
        float4 a2 = *(const float4*)&kb[i4.z*96 + ch];
        float4 a3 = *(const float4*)&kb[i4.w*96 + ch];
        ks[(d0+0)*52 + j] = w4.x*a0.x + w4.y*a1.x + w4.z*a2.x + w4.w*a3.x;
        ks[(d0+1)*52 + j] = w4.x*a0.y + w4.y*a1.y + w4.z*a2.y + w4.w*a3.y;
        ks[(d0+2)*52 + j] = w4.x*a0.z + w4.y*a1.z + w4.z*a2.z + w4.w*a3.z;
        ks[(d0+3)*52 + j] = w4.x*a0.w + w4.y*a1.w + w4.z*a2.w + w4.w*a3.w;

        float4 b0 = *(const float4*)&vb[i4.x*96 + ch];
        float4 b1 = *(const float4*)&vb[i4.y*96 + ch];
        float4 b2 = *(const float4*)&vb[i4.z*96 + ch];
        float4 b3 = *(const float4*)&vb[i4.w*96 + ch];
        *(float4*)&vs[j*36 + d0] = make_float4(
            w4.x*b0.x + w4.y*b1.x + w4.z*b2.x + w4.w*b3.x,
            w4.x*b0.y + w4.y*b1.y + w4.z*b2.y + w4.w*b3.y,
            w4.x*b0.z + w4.y*b1.z + w4.z*b2.z + w4.w*b3.z,
            w4.x*b0.w + w4.y*b1.w + w4.z*b2.w + w4.w*b3.w);
    }
    __syncthreads();

    // dots = q @ k^T + bias -> at[k][q] (transposed)
    for (int t2 = tid; t2 < 169; t2 += 128) {
        int ti = t2/13, tk = t2 - ti*13;
        int q0 = ti*4, k0 = tk*4;
        unsigned long long acc[4][2] = {{0,0},{0,0},{0,0},{0,0}};
        #pragma unroll 8
        for (int d = 0; d < DH; d++) {
            float4 qv = *(float4*)&qs[d*52 + q0];
            float4 kv = *(float4*)&ks[d*52 + k0];
            unsigned long long kA = pk2(kv.x, kv.y), kB = pk2(kv.z, kv.w);
            unsigned long long qd;
            qd = pk2(qv.x, qv.x); fma2(acc[0][0], qd, kA); fma2(acc[0][1], qd, kB);
            qd = pk2(qv.y, qv.y); fma2(acc[1][0], qd, kA); fma2(acc[1][1], qd, kB);
            qd = pk2(qv.z, qv.z); fma2(acc[2][0], qd, kA); fma2(acc[2][1], qd, kB);
            qd = pk2(qv.w, qv.w); fma2(acc[3][0], qd, kA); fma2(acc[3][1], qd, kB);
        }
        #pragma unroll
        for (int i = 0; i < 4; i++) {
            int qi = q0 + i; if (qi >= 49) break;
            int qr = qi/7, qsx = qi - qr*7;
            #pragma unroll
            for (int jp = 0; jp < 2; jp++) {
                float f0, f1; unpk2(acc[i][jp], f0, f1);
                int ki = k0 + jp*2;
                if (ki <= 48) {
                    int kr = ki/7, ksx = ki - kr*7;
                    at[ki*52 + qi] = f0 + rpbs[(qr - kr + 6)*13 + (qsx - ksx + 6)];
                }
                ki++;
                if (ki <= 48) {
                    int kr = ki/7, ksx = ki - kr*7;
                    at[ki*52 + qi] = f1 + rpbs[(qr - kr + 6)*13 + (qsx - ksx + 6)];
                }
            }
        }
    }
    __syncthreads();

    // softmax over k per q (column q of at)
    if (tid < 49) {
        float m = -1e30f;
        for (int k2 = 0; k2 < 49; k2++) m = fmaxf(m, at[k2*52 + tid]);
        float sum = 0.f;
        for (int k2 = 0; k2 < 49; k2++) {
            float e = __expf(at[k2*52 + tid] - m);
            at[k2*52 + tid] = e;
            sum += e;
        }
        float inv = 1.f/sum;
        for (int k2 = 0; k2 < 49; k2++) at[k2*52 + tid] *= inv;
    }
    __syncthreads();

    // out = attn @ v ; output store = aligned float4 into ao[pix][96]
    float* ob = g_ao + (size_t)b*NPIX*96;
    for (int t2 = tid; t2 < 104; t2 += 128) {
        int jt = t2 >> 3, dt = t2 & 7;
        int j0 = jt*4, d0 = dt*4;
        unsigned long long acc[4][2] = {{0,0},{0,0},{0,0},{0,0}};
        #pragma unroll 7
        for (int ki = 0; ki < 49; ki++) {
            float4 av = *(float4*)&at[ki*52 + j0];
            float4 vv = *(float4*)&vs[ki*36 + d0];
            unsigned long long vA = pk2(vv.x, vv.y), vB = pk2(vv.z, vv.w);
            unsigned long long ad;
            ad = pk2(av.x, av.x); fma2(acc[0][0], ad, vA); fma2(acc[0][1], ad, vB);
            ad = pk2(av.y, av.y); fma2(acc[1][0], ad, vA); fma2(acc[1][1], ad, vB);
            ad = pk2(av.z, av.z); fma2(acc[2][0], ad, vA); fma2(acc[2][1], ad, vB);
            ad = pk2(av.w, av.w); fma2(acc[3][0], ad, vA); fma2(acc[3][1], ad, vB);
        }
        #pragma unroll
        for (int i = 0; i < 4; i++) {
            int j = j0 + i; if (j >= 49) break;
            int r = j/7, s = j - r*7;
            int pix = (y0 + r)*WW + x0 + s;
            float f0, f1, f2, f3;
            unpk2(acc[i][0], f0, f1);
            unpk2(acc[i][1], f2, f3);
            *(float4*)&ob[pix*96 + chb + d0] = make_float4(f0, f1, f2, f3);
        }
    }
}

// ---------------------------------------------------------------------------
// Kernel 5: output projection GEMM (+bias) -> d_out (layout [b][c][pix]).
// x-tile loaded c-major from ao[pix][96] (pad smem rows to 132).
// ---------------------------------------------------------------------------
__global__ __launch_bounds__(128) void k_proj(const float* __restrict__ w_proj,
                                              const float* __restrict__ b_proj,
                                              float* __restrict__ out) {
    int pix0 = blockIdx.x*128;
    int b = blockIdx.y;

    __shared__ __align__(16) float xs[16][132];
    __shared__ __align__(16) float ws[16][100];

    int t = threadIdx.x;
    int pg = t & 15;
    int og = t >> 4;

    unsigned long long acc[12][4];
    #pragma unroll
    for (int i = 0; i < 12; i++) {
        float bb = b_proj[og*12 + i];
        unsigned long long p = pk2(bb, bb);
        #pragma unroll
        for (int j = 0; j < 4; j++) acc[i][j] = p;
    }

    const float* ab = g_ao + (size_t)b*NPIX*96;
    for (int kc = 0; kc < 6; kc++) {
        #pragma unroll
        for (int it = 0; it < 12; it++) {
            int idx = t + it*128;
            int o = idx >> 4, kk = idx & 15;
            ws[kk][o] = w_proj[o*96 + kc*16 + kk];
        }
        #pragma unroll
        for (int it = 0; it < 4; it++) {
            int idx4 = t + it*128;
            int p = idx4 >> 2, cq = idx4 & 3;
            float4 v = *(const float4*)&ab[(pix0 + p)*96 + kc*16 + cq*4];
            xs[cq*4+0][p] = v.x;
            xs[cq*4+1][p] = v.y;
            xs[cq*4+2][p] = v.z;
            xs[cq*4+3][p] = v.w;
        }
        __syncthreads();
        #pragma unroll 4
        for (int kk = 0; kk < 16; kk++) {
            float4 xa = *(float4*)&xs[kk][pg*8];
            float4 xb = *(float4*)&xs[kk][pg*8 + 4];
            unsigned long long xv[4] = { pk2(xa.x, xa.y), pk2(xa.z, xa.w),
                                         pk2(xb.x, xb.y), pk2(xb.z, xb.w) };
            float4 w0 = *(float4*)&ws[kk][og*12];
            float4 w1 = *(float4*)&ws[kk][og*12 + 4];
            float4 w2 = *(float4*)&ws[kk][og*12 + 8];
            float wv[12] = { w0.x,w0.y,w0.z,w0.w, w1.x,w1.y,w1.z,w1.w,
                             w2.x,w2.y,w2.z,w2.w };
            #pragma unroll
            for (int i = 0; i < 12; i++) {
                unsigned long long wd = pk2(wv[i], wv[i]);
                #pragma unroll
                for (int j = 0; j < 4; j++) fma2(acc[i][j], wd, xv[j]);
            }
        }
        __syncthreads();
    }
    #pragma unroll
    for (int i = 0; i < 12; i++) {
        float f[8];
        #pragma unroll
        for (int j = 0; j < 4; j++) unpk2(acc[i][j], f[2*j], f[2*j+1]);
        float* op = out + (b*CC + og*12 + i)*NPIX + pix0 + pg*8;
        *(float4*)op       = make_float4(f[0], f[1], f[2], f[3]);
        *(float4*)(op + 4) = make_float4(f[4], f[5], f[6], f[7]);
    }
}

// ---------------------------------------------------------------------------
extern "C" void kernel_launch(void* const* d_in, const int* in_sizes, int n_in,
                              void* d_out, int out_size) {
    const float* x      = (const float*)d_in[0];
    const float* w_qkv  = (const float*)d_in[1];
    const float* b_qkv  = (const float*)d_in[2];
    const float* w_off  = (const float*)d_in[3];
    const float* b_off  = (const float*)d_in[4];
    const float* w_scl  = (const float*)d_in[5];
    const float* b_scl  = (const float*)d_in[6];
    const float* rpb    = (const float*)d_in[7];
    const float* w_proj = (const float*)d_in[8];
    const float* b_proj = (const float*)d_in[9];
    float* out = (float*)d_out;

    k_pool  <<<dim3(WN, CC, BB), 128>>>(x);
    k_offscl<<<dim3(NWIN, BB), 128>>>(w_off, b_off, w_scl, b_scl);
    k_qkv   <<<dim3(NPIX/128, 3, BB), 128>>>(x, w_qkv, b_qkv);
    k_attn  <<<dim3(NWIN, HEADS, BB), 128>>>(rpb);
    k_proj  <<<dim3(NPIX/128, BB), 128>>>(w_proj, b_proj, out);
}